// round 4
// baseline (speedup 1.0000x reference)
#include <cuda_runtime.h>
#include <math.h>

#define B_DIM 64
#define C_DIM 64
#define K_CL 8
#define HW 12544            // 112*112
#define HW4 3136            // HW/4
#define BC (B_DIM * C_DIM)  // 4096
#define EPS 1e-6f
#define GRID_MAIN 296       // 2 blocks/SM on 148 SMs

// ---- device scratch (no allocation allowed) -------------------------------
__device__ int   g_cid[B_DIM];
__device__ float g_lmda[B_DIM];
__device__ int   g_count[K_CL];          // members per cluster
__device__ int   g_plane_order[BC];      // planes sorted by cluster
__device__ int   g_task_cluster[BC];     // cluster id of each ordered task
__device__ float g_s1[BC];
__device__ float g_s2[BC];
__device__ float g_scale[BC];
__device__ float g_bias[BC];
__device__ int   g_done[K_CL];           // completed moments tasks per cluster
__device__ int   g_flag[K_CL];           // stats ready
__device__ int   g_mtask;                // moments task cursor
__device__ int   g_atask;                // apply task cursor

// ---------------------------------------------------------------------------
// Kernel A: schedule. cid/argmax, cluster-ordered plane list, counter resets.
// ---------------------------------------------------------------------------
__global__ __launch_bounds__(256) void k_schedule(const float* __restrict__ cluster_map,
                                                  const float* __restrict__ lmda) {
    __shared__ int sh_cid[B_DIM];
    __shared__ int sh_sorted_b[B_DIM];   // samples ordered by cluster
    __shared__ int sh_cnt[K_CL];

    const int tid = threadIdx.x;

    if (tid < B_DIM) {
        const float* row = cluster_map + tid * K_CL;
        float best = row[0];
        int bi = 0;
#pragma unroll
        for (int k = 1; k < K_CL; ++k) {
            float v = row[k];
            if (v > best) { best = v; bi = k; }
        }
        sh_cid[tid] = bi;
        g_cid[tid] = bi;
        g_lmda[tid] = lmda[tid];
    }
    __syncthreads();

    // serial ordering by one thread (64 samples — trivial)
    if (tid == 0) {
        int pos = 0;
        for (int k = 0; k < K_CL; ++k) {
            int c = 0;
            for (int b = 0; b < B_DIM; ++b) {
                if (sh_cid[b] == k) { sh_sorted_b[pos++] = b; ++c; }
            }
            sh_cnt[k] = c;
            g_count[k] = c;
            g_done[k] = 0;
            g_flag[k] = (c == 0) ? 1 : 0;
        }
        g_mtask = 0;
        g_atask = 0;
    }
    __syncthreads();

    // fill the 4096-entry task list: member-major, 64 channels each
    for (int i = tid; i < BC; i += 256) {
        int b = sh_sorted_b[i >> 6];
        int c = i & 63;
        g_plane_order[i] = b * C_DIM + c;
        g_task_cluster[i] = sh_cid[b];
    }
}

// ---------------------------------------------------------------------------
// Kernel B: persistent dataflow. Moments + per-cluster stats + apply, with
// apply prioritized as soon as its cluster's stats flag is up (L2-hot reuse).
// ---------------------------------------------------------------------------
__global__ __launch_bounds__(256) void k_main(const float* __restrict__ x,
                                              float* __restrict__ out) {
    __shared__ int sh_task;
    __shared__ int sh_type;     // 0=moments, 1=apply(ready), 2=apply(spin), 3=exit
    __shared__ int sh_do_stats;
    __shared__ float sh1[8], sh2[8];

    const int tid = threadIdx.x;
    const int lane = tid & 31;
    const int wid = tid >> 5;

    for (;;) {
        if (tid == 0) {
            int task = -1, type = 0;
            // Prefer the head apply task if its cluster stats are ready.
            int at = *(volatile int*)&g_atask;
            if (at < BC) {
                int k = g_task_cluster[at];
                if (*(volatile int*)&g_flag[k]) {
                    if (atomicCAS(&g_atask, at, at + 1) == at) { task = at; type = 1; }
                }
            }
            if (task < 0) {
                int mt = atomicAdd(&g_mtask, 1);
                if (mt < BC) { task = mt; type = 0; }
                else {
                    int a2 = atomicAdd(&g_atask, 1);
                    if (a2 < BC) { task = a2; type = 2; }
                    else { type = 3; }
                }
            }
            sh_task = task;
            sh_type = type;
        }
        __syncthreads();
        const int type = sh_type;
        const int task = sh_task;
        if (type == 3) return;

        const int plane = g_plane_order[task];
        const int kcl = g_task_cluster[task];

        if (type == 0) {
            // ---------------- moments for one plane ----------------
            const float4* __restrict__ p =
                reinterpret_cast<const float4*>(x + (size_t)plane * HW);
            float s1 = 0.f, s2 = 0.f;
#pragma unroll 4
            for (int i = tid; i < HW4; i += 256) {
                float4 v = p[i];   // evict-normal: persist for apply
                s1 += (v.x + v.y) + (v.z + v.w);
                s2 += (v.x * v.x + v.y * v.y) + (v.z * v.z + v.w * v.w);
            }
#pragma unroll
            for (int off = 16; off > 0; off >>= 1) {
                s1 += __shfl_down_sync(0xffffffffu, s1, off);
                s2 += __shfl_down_sync(0xffffffffu, s2, off);
            }
            if (lane == 0) { sh1[wid] = s1; sh2[wid] = s2; }
            __syncthreads();
            if (tid == 0) {
                float t1 = 0.f, t2 = 0.f;
#pragma unroll
                for (int w = 0; w < 8; ++w) { t1 += sh1[w]; t2 += sh2[w]; }
                g_s1[plane] = t1;
                g_s2[plane] = t2;
                __threadfence();
                int total = g_count[kcl] * C_DIM;
                int old = atomicAdd(&g_done[kcl], 1);
                sh_do_stats = (old == total - 1) ? 1 : 0;
            }
            __syncthreads();

            if (sh_do_stats) {
                // -------- this block computes cluster kcl's stats + affine --
                __threadfence();   // acquire side: see all members' s1/s2
                if (tid < C_DIM) {
                    const int c = tid;
                    float cs1 = 0.f, cs2 = 0.f;
#pragma unroll
                    for (int b = 0; b < B_DIM; ++b) {
                        if (g_cid[b] == kcl) {
                            cs1 += __ldcg(&g_s1[b * C_DIM + c]);
                            cs2 += __ldcg(&g_s2[b * C_DIM + c]);
                        }
                    }
                    float cnt = (float)g_count[kcl];
                    float n_k = fmaxf(cnt * (float)HW, 1.0f);
                    float cmu = cs1 / n_k;
                    float cvar = (cs2 - n_k * cmu * cmu) / fmaxf(n_k - 1.0f, 1.0f);
                    float cstd = sqrtf(cvar + EPS);

                    const float inv_n = 1.0f / (float)HW;
                    const float inv_nm1 = 1.0f / (float)(HW - 1);
#pragma unroll
                    for (int b = 0; b < B_DIM; ++b) {
                        if (g_cid[b] == kcl) {
                            int bc = b * C_DIM + c;
                            float s1v = __ldcg(&g_s1[bc]);
                            float s2v = __ldcg(&g_s2[bc]);
                            float smu = s1v * inv_n;
                            float svar = (s2v - (float)HW * smu * smu) * inv_nm1;
                            float sstd = sqrtf(svar + EPS);
                            float l = g_lmda[b];
                            float std_mix = sstd * l + cstd * (1.0f - l);
                            float mu_mix = smu * l + cmu * (1.0f - l);
                            float scale = std_mix / sstd;
                            g_scale[bc] = scale;
                            g_bias[bc] = mu_mix - smu * scale;
                        }
                    }
                }
                __syncthreads();
                if (tid == 0) {
                    __threadfence();
                    atomicExch(&g_flag[kcl], 1);
                }
            }
        } else {
            // ---------------- apply for one plane ----------------
            if (type == 2) {
                if (tid == 0) {
                    while (!(*(volatile int*)&g_flag[kcl])) __nanosleep(64);
                }
                __syncthreads();
            }
            __threadfence();  // see stats writer's scale/bias
            const float scale = __ldcg(&g_scale[plane]);
            const float bias = __ldcg(&g_bias[plane]);
            const float4* __restrict__ px =
                reinterpret_cast<const float4*>(x + (size_t)plane * HW);
            float4* __restrict__ po =
                reinterpret_cast<float4*>(out + (size_t)plane * HW);
#pragma unroll 4
            for (int i = tid; i < HW4; i += 256) {
                float4 v = __ldcs(&px[i]);   // hot in L2, dead afterwards
                v.x = fmaf(v.x, scale, bias);
                v.y = fmaf(v.y, scale, bias);
                v.z = fmaf(v.z, scale, bias);
                v.w = fmaf(v.w, scale, bias);
                __stcs(&po[i], v);           // streaming store
            }
        }
        __syncthreads();
    }
}

extern "C" void kernel_launch(void* const* d_in, const int* in_sizes, int n_in,
                              void* d_out, int out_size) {
    const float* x = (const float*)d_in[0];            // [64,64,112,112]
    const float* cluster_map = (const float*)d_in[1];  // [1,64,8]
    const float* lmda = (const float*)d_in[2];         // [64,1,1,1]
    float* out = (float*)d_out;

    k_schedule<<<1, 256>>>(cluster_map, lmda);
    k_main<<<GRID_MAIN, 256>>>(x, out);
}

// round 5
// speedup vs baseline: 2.0037x; 2.0037x over previous
#include <cuda_runtime.h>
#include <math.h>

#define B_DIM 64
#define C_DIM 64
#define K_CL 8
#define HW 12544            // 112*112
#define HW4 3136            // HW/4
#define BC (B_DIM * C_DIM)  // 4096
#define EPS 1e-6f
#define GRID_MAIN 1184      // 8 blocks/SM * 148 SMs -> 64 warps/SM

// ---- device scratch (no allocation allowed) -------------------------------
__device__ int   g_cid[B_DIM];
__device__ float g_lmda[B_DIM];
__device__ int   g_count[K_CL];          // members per cluster
__device__ int   g_plane_order[BC];      // planes sorted by cluster
__device__ int   g_task_cluster[BC];     // cluster id of each ordered task
__device__ float g_s1[BC];
__device__ float g_s2[BC];
__device__ float g_scale[BC];
__device__ float g_bias[BC];
__device__ int   g_done[K_CL];           // completed moments tasks per cluster
__device__ int   g_flag[K_CL];           // stats ready
__device__ int   g_mtask;                // moments task cursor
__device__ int   g_atask;                // apply task cursor

// ---------------------------------------------------------------------------
// Kernel A: schedule. cid/argmax, cluster-ordered plane list, counter resets.
// ---------------------------------------------------------------------------
__global__ __launch_bounds__(256) void k_schedule(const float* __restrict__ cluster_map,
                                                  const float* __restrict__ lmda) {
    __shared__ int sh_cid[B_DIM];
    __shared__ int sh_sorted_b[B_DIM];

    const int tid = threadIdx.x;

    if (tid < B_DIM) {
        const float* row = cluster_map + tid * K_CL;
        float best = row[0];
        int bi = 0;
#pragma unroll
        for (int k = 1; k < K_CL; ++k) {
            float v = row[k];
            if (v > best) { best = v; bi = k; }
        }
        sh_cid[tid] = bi;
        g_cid[tid] = bi;
        g_lmda[tid] = lmda[tid];
    }
    __syncthreads();

    if (tid == 0) {
        int pos = 0;
        for (int k = 0; k < K_CL; ++k) {
            int c = 0;
            for (int b = 0; b < B_DIM; ++b) {
                if (sh_cid[b] == k) { sh_sorted_b[pos++] = b; ++c; }
            }
            g_count[k] = c;
            g_done[k] = 0;
            g_flag[k] = (c == 0) ? 1 : 0;
        }
        g_mtask = 0;
        g_atask = 0;
    }
    __syncthreads();

    for (int i = tid; i < BC; i += 256) {
        int b = sh_sorted_b[i >> 6];
        int c = i & 63;
        g_plane_order[i] = b * C_DIM + c;
        g_task_cluster[i] = sh_cid[b];
    }
}

// ---------------------------------------------------------------------------
// Kernel B: persistent dataflow, full occupancy (8 CTA/SM).
// ---------------------------------------------------------------------------
__global__ __launch_bounds__(256, 8) void k_main(const float* __restrict__ x,
                                                 float* __restrict__ out) {
    __shared__ int sh_task;
    __shared__ int sh_type;     // 0=moments, 1=apply, 2=apply(spin), 3=exit
    __shared__ int sh_do_stats;
    __shared__ float sh1[8], sh2[8];

    const int tid = threadIdx.x;
    const int lane = tid & 31;
    const int wid = tid >> 5;

    for (;;) {
        if (tid == 0) {
            int task = -1, type = 0;
            // Prefer head apply task if its cluster stats are ready (L2-hot).
            int at = *(volatile int*)&g_atask;
            if (at < BC) {
                int k = g_task_cluster[at];
                if (*(volatile int*)&g_flag[k]) {
                    if (atomicCAS(&g_atask, at, at + 1) == at) { task = at; type = 1; }
                }
            }
            if (task < 0) {
                int mt = atomicAdd(&g_mtask, 1);
                if (mt < BC) { task = mt; type = 0; }
                else {
                    int a2 = atomicAdd(&g_atask, 1);
                    if (a2 < BC) { task = a2; type = 2; }
                    else { type = 3; }
                }
            }
            sh_task = task;
            sh_type = type;
        }
        __syncthreads();
        const int type = sh_type;
        const int task = sh_task;
        if (type == 3) return;

        const int plane = g_plane_order[task];
        const int kcl = g_task_cluster[task];

        if (type == 0) {
            // ---------------- moments for one plane ----------------
            const float4* __restrict__ p =
                reinterpret_cast<const float4*>(x + (size_t)plane * HW);
            float s1 = 0.f, s2 = 0.f;
#pragma unroll 4
            for (int i = tid; i < HW4; i += 256) {
                float4 v = p[i];   // evict-normal: persist in L2 for apply
                s1 += (v.x + v.y) + (v.z + v.w);
                s2 += (v.x * v.x + v.y * v.y) + (v.z * v.z + v.w * v.w);
            }
#pragma unroll
            for (int off = 16; off > 0; off >>= 1) {
                s1 += __shfl_down_sync(0xffffffffu, s1, off);
                s2 += __shfl_down_sync(0xffffffffu, s2, off);
            }
            if (lane == 0) { sh1[wid] = s1; sh2[wid] = s2; }
            __syncthreads();
            if (tid == 0) {
                float t1 = 0.f, t2 = 0.f;
#pragma unroll
                for (int w = 0; w < 8; ++w) { t1 += sh1[w]; t2 += sh2[w]; }
                g_s1[plane] = t1;
                g_s2[plane] = t2;
                __threadfence();   // publish s1/s2 before done-count
                int total = g_count[kcl] * C_DIM;
                int old = atomicAdd(&g_done[kcl], 1);
                sh_do_stats = (old == total - 1) ? 1 : 0;
            }
            __syncthreads();

            if (sh_do_stats) {
                // ---- last finisher computes cluster stats + fused affine ----
                __threadfence();   // acquire: see all members' s1/s2
                if (tid < C_DIM) {
                    const int c = tid;
                    float cs1 = 0.f, cs2 = 0.f;
#pragma unroll
                    for (int b = 0; b < B_DIM; ++b) {
                        if (g_cid[b] == kcl) {
                            cs1 += __ldcg(&g_s1[b * C_DIM + c]);
                            cs2 += __ldcg(&g_s2[b * C_DIM + c]);
                        }
                    }
                    float cnt = (float)g_count[kcl];
                    float n_k = fmaxf(cnt * (float)HW, 1.0f);
                    float cmu = cs1 / n_k;
                    float cvar = (cs2 - n_k * cmu * cmu) / fmaxf(n_k - 1.0f, 1.0f);
                    float cstd = sqrtf(cvar + EPS);

                    const float inv_n = 1.0f / (float)HW;
                    const float inv_nm1 = 1.0f / (float)(HW - 1);
#pragma unroll
                    for (int b = 0; b < B_DIM; ++b) {
                        if (g_cid[b] == kcl) {
                            int bc = b * C_DIM + c;
                            float s1v = __ldcg(&g_s1[bc]);
                            float s2v = __ldcg(&g_s2[bc]);
                            float smu = s1v * inv_n;
                            float svar = (s2v - (float)HW * smu * smu) * inv_nm1;
                            float sstd = sqrtf(svar + EPS);
                            float l = g_lmda[b];
                            float std_mix = sstd * l + cstd * (1.0f - l);
                            float mu_mix = smu * l + cmu * (1.0f - l);
                            float scale = std_mix / sstd;
                            g_scale[bc] = scale;
                            g_bias[bc] = mu_mix - smu * scale;
                        }
                    }
                }
                __syncthreads();
                if (tid == 0) {
                    __threadfence();           // publish scale/bias
                    atomicExch(&g_flag[kcl], 1);
                }
            }
        } else {
            // ---------------- apply for one plane ----------------
            if (type == 2) {
                if (tid == 0) {
                    while (!(*(volatile int*)&g_flag[kcl])) __nanosleep(64);
                }
                __syncthreads();   // ordering: flag observed before reads below
            }
            // scale/bias read via L2 (__ldcg): writer fenced them to L2 before
            // raising the flag, and the flag was checked before dequeue/here.
            const float scale = __ldcg(&g_scale[plane]);
            const float bias = __ldcg(&g_bias[plane]);
            const float4* __restrict__ px =
                reinterpret_cast<const float4*>(x + (size_t)plane * HW);
            float4* __restrict__ po =
                reinterpret_cast<float4*>(out + (size_t)plane * HW);
#pragma unroll 4
            for (int i = tid; i < HW4; i += 256) {
                float4 v = __ldcs(&px[i]);   // hot in L2, dead afterwards
                v.x = fmaf(v.x, scale, bias);
                v.y = fmaf(v.y, scale, bias);
                v.z = fmaf(v.z, scale, bias);
                v.w = fmaf(v.w, scale, bias);
                __stcs(&po[i], v);           // streaming store
            }
        }
        __syncthreads();
    }
}

extern "C" void kernel_launch(void* const* d_in, const int* in_sizes, int n_in,
                              void* d_out, int out_size) {
    const float* x = (const float*)d_in[0];            // [64,64,112,112]
    const float* cluster_map = (const float*)d_in[1];  // [1,64,8]
    const float* lmda = (const float*)d_in[2];         // [64,1,1,1]
    float* out = (float*)d_out;

    k_schedule<<<1, 256>>>(cluster_map, lmda);
    k_main<<<GRID_MAIN, 256>>>(x, out);
}

// round 6
// speedup vs baseline: 2.0692x; 1.0327x over previous
#include <cuda_runtime.h>
#include <math.h>

#define B_DIM 64
#define C_DIM 64
#define K_CL 8
#define HW 12544            // 112*112
#define HW4 3136            // HW/4
#define BC (B_DIM * C_DIM)  // 4096
#define NTASK_M (BC / 2)    // moments tasks, 2 planes each
#define EPS 1e-6f
#define GRID_MAIN 1184      // 8 blocks/SM * 148 SMs

// ---- device scratch -------------------------------------------------------
__device__ int   g_cid[B_DIM];
__device__ float g_lmda[B_DIM];
__device__ int   g_count[K_CL];
__device__ int   g_plane_order[BC];
__device__ int   g_task_cluster[BC];
__device__ float g_s1[BC];
__device__ float g_s2[BC];
__device__ float g_scale[BC];
__device__ float g_bias[BC];
__device__ int   g_done[K_CL];
__device__ int   g_flag[K_CL];
__device__ int   g_mtask;
__device__ int   g_atask;

// ---------------------------------------------------------------------------
// Kernel A: schedule — fully parallel (no serial thread-0 sort).
// ---------------------------------------------------------------------------
__global__ __launch_bounds__(256) void k_schedule(const float* __restrict__ cluster_map,
                                                  const float* __restrict__ lmda) {
    __shared__ int sh_cid[B_DIM];
    __shared__ int sh_sorted_b[B_DIM];
    __shared__ int sh_off[K_CL];
    __shared__ int sh_cnt[K_CL];

    const int tid = threadIdx.x;

    if (tid < B_DIM) {
        const float* row = cluster_map + tid * K_CL;
        float best = row[0];
        int bi = 0;
#pragma unroll
        for (int k = 1; k < K_CL; ++k) {
            float v = row[k];
            if (v > best) { best = v; bi = k; }
        }
        sh_cid[tid] = bi;
        g_cid[tid] = bi;
        g_lmda[tid] = lmda[tid];
    }
    __syncthreads();

    if (tid < K_CL) {
        int c = 0;
#pragma unroll
        for (int b = 0; b < B_DIM; ++b) c += (sh_cid[b] == tid);
        sh_cnt[tid] = c;
        g_count[tid] = c;
        g_done[tid] = 0;
        g_flag[tid] = (c == 0) ? 1 : 0;
    }
    __syncthreads();

    if (tid == 0) {
        int acc = 0;
#pragma unroll
        for (int k = 0; k < K_CL; ++k) { sh_off[k] = acc; acc += sh_cnt[k]; }
        g_mtask = 0;
        g_atask = 0;
    }
    __syncthreads();

    if (tid < K_CL) {
        int pos = sh_off[tid];
#pragma unroll
        for (int b = 0; b < B_DIM; ++b)
            if (sh_cid[b] == tid) sh_sorted_b[pos++] = b;
    }
    __syncthreads();

    for (int i = tid; i < BC; i += 256) {
        int b = sh_sorted_b[i >> 6];
        g_plane_order[i] = b * C_DIM + (i & 63);
        g_task_cluster[i] = sh_cid[b];
    }
}

// ---------------------------------------------------------------------------
// block-wide moments of one plane; result valid on tid 0.
// ---------------------------------------------------------------------------
__device__ __forceinline__ void plane_moments(const float* __restrict__ x, int plane,
                                              float* sh1, float* sh2,
                                              float& out_s1, float& out_s2) {
    const int tid = threadIdx.x;
    const int lane = tid & 31;
    const int wid = tid >> 5;
    const float4* __restrict__ p =
        reinterpret_cast<const float4*>(x + (size_t)plane * HW);
    float s1 = 0.f, s2 = 0.f;
#pragma unroll 4
    for (int i = tid; i < HW4; i += 256) {
        float4 v = p[i];
        s1 += (v.x + v.y) + (v.z + v.w);
        s2 += (v.x * v.x + v.y * v.y) + (v.z * v.z + v.w * v.w);
    }
#pragma unroll
    for (int off = 16; off > 0; off >>= 1) {
        s1 += __shfl_down_sync(0xffffffffu, s1, off);
        s2 += __shfl_down_sync(0xffffffffu, s2, off);
    }
    if (lane == 0) { sh1[wid] = s1; sh2[wid] = s2; }
    __syncthreads();
    if (tid == 0) {
        float t1 = 0.f, t2 = 0.f;
#pragma unroll
        for (int w = 0; w < 8; ++w) { t1 += sh1[w]; t2 += sh2[w]; }
        out_s1 = t1; out_s2 = t2;
    }
    __syncthreads();
}

// once-per-cluster stats + fused affine params (called by the finisher block)
__device__ __forceinline__ void cluster_stats(int kcl) {
    const int tid = threadIdx.x;
    __threadfence();   // acquire: see all members' s1/s2
    if (tid < C_DIM) {
        const int c = tid;
        float cs1 = 0.f, cs2 = 0.f;
#pragma unroll
        for (int b = 0; b < B_DIM; ++b) {
            if (g_cid[b] == kcl) {
                cs1 += __ldcg(&g_s1[b * C_DIM + c]);
                cs2 += __ldcg(&g_s2[b * C_DIM + c]);
            }
        }
        float cnt = (float)g_count[kcl];
        float n_k = fmaxf(cnt * (float)HW, 1.0f);
        float cmu = cs1 / n_k;
        float cvar = (cs2 - n_k * cmu * cmu) / fmaxf(n_k - 1.0f, 1.0f);
        float cstd = sqrtf(cvar + EPS);

        const float inv_n = 1.0f / (float)HW;
        const float inv_nm1 = 1.0f / (float)(HW - 1);
#pragma unroll
        for (int b = 0; b < B_DIM; ++b) {
            if (g_cid[b] == kcl) {
                int bc = b * C_DIM + c;
                float s1v = __ldcg(&g_s1[bc]);
                float s2v = __ldcg(&g_s2[bc]);
                float smu = s1v * inv_n;
                float svar = (s2v - (float)HW * smu * smu) * inv_nm1;
                float sstd = sqrtf(svar + EPS);
                float l = g_lmda[b];
                float std_mix = sstd * l + cstd * (1.0f - l);
                float mu_mix = smu * l + cmu * (1.0f - l);
                float scale = std_mix / sstd;
                g_scale[bc] = scale;
                g_bias[bc] = mu_mix - smu * scale;
            }
        }
    }
    __syncthreads();
    if (tid == 0) {
        __threadfence();
        atomicExch(&g_flag[kcl], 1);
    }
    __syncthreads();
}

// ---------------------------------------------------------------------------
// Kernel B: persistent dataflow. Moments (batched x2) + stats + apply.
// ---------------------------------------------------------------------------
__global__ __launch_bounds__(256, 8) void k_main(const float* __restrict__ x,
                                                 float* __restrict__ out) {
    __shared__ int sh_task;
    __shared__ int sh_type;     // 0=moments(2 planes), 1=apply, 2=apply(spin), 3=exit
    __shared__ int sh_stats0, sh_stats1;
    __shared__ float sh1[8], sh2[8];

    const int tid = threadIdx.x;

    for (;;) {
        if (tid == 0) {
            int task = -1, type = 0;
            int at = *(volatile int*)&g_atask;
            if (at < BC) {
                int k = g_task_cluster[at];
                if (*(volatile int*)&g_flag[k]) {
                    if (atomicCAS(&g_atask, at, at + 1) == at) { task = at; type = 1; }
                }
            }
            if (task < 0) {
                int mt = atomicAdd(&g_mtask, 1);
                if (mt < NTASK_M) { task = mt; type = 0; }
                else {
                    int a2 = atomicAdd(&g_atask, 1);
                    if (a2 < BC) { task = a2; type = 2; }
                    else { type = 3; }
                }
            }
            sh_task = task;
            sh_type = type;
        }
        __syncthreads();
        const int type = sh_type;
        const int task = sh_task;
        if (type == 3) return;

        if (type == 0) {
            // ----------- moments for two consecutive ordered planes -----------
            const int i0 = task * 2, i1 = task * 2 + 1;
            const int p0 = g_plane_order[i0], p1 = g_plane_order[i1];
            const int k0 = g_task_cluster[i0], k1 = g_task_cluster[i1];

            float a1, a2v, b1, b2v;
            plane_moments(x, p0, sh1, sh2, a1, a2v);
            plane_moments(x, p1, sh1, sh2, b1, b2v);

            if (tid == 0) {
                g_s1[p0] = a1; g_s2[p0] = a2v;
                g_s1[p1] = b1; g_s2[p1] = b2v;
                __threadfence();   // publish before done-counts
                int fin0 = 0, fin1 = 0;
                if (k0 == k1) {
                    int total = g_count[k0] * C_DIM;
                    fin0 = (atomicAdd(&g_done[k0], 2) == total - 2);
                } else {
                    int t0 = g_count[k0] * C_DIM;
                    int t1 = g_count[k1] * C_DIM;
                    fin0 = (atomicAdd(&g_done[k0], 1) == t0 - 1);
                    fin1 = (atomicAdd(&g_done[k1], 1) == t1 - 1);
                }
                sh_stats0 = fin0;
                sh_stats1 = fin1;
            }
            __syncthreads();
            if (sh_stats0) cluster_stats(k0);
            if (sh_stats1) cluster_stats(k1);
        } else {
            // ---------------- apply for one plane ----------------
            const int plane = g_plane_order[task];
            const int kcl = g_task_cluster[task];
            if (type == 2) {
                if (tid == 0) {
                    while (!(*(volatile int*)&g_flag[kcl])) __nanosleep(64);
                }
                __syncthreads();
            }
            const float scale = __ldcg(&g_scale[plane]);
            const float bias = __ldcg(&g_bias[plane]);
            const float4* __restrict__ px =
                reinterpret_cast<const float4*>(x + (size_t)plane * HW);
            float4* __restrict__ po =
                reinterpret_cast<float4*>(out + (size_t)plane * HW);
#pragma unroll 4
            for (int i = tid; i < HW4; i += 256) {
                float4 v = __ldcs(&px[i]);
                v.x = fmaf(v.x, scale, bias);
                v.y = fmaf(v.y, scale, bias);
                v.z = fmaf(v.z, scale, bias);
                v.w = fmaf(v.w, scale, bias);
                __stcs(&po[i], v);
            }
        }
        __syncthreads();
    }
}

extern "C" void kernel_launch(void* const* d_in, const int* in_sizes, int n_in,
                              void* d_out, int out_size) {
    const float* x = (const float*)d_in[0];            // [64,64,112,112]
    const float* cluster_map = (const float*)d_in[1];  // [1,64,8]
    const float* lmda = (const float*)d_in[2];         // [64,1,1,1]
    float* out = (float*)d_out;

    k_schedule<<<1, 256>>>(cluster_map, lmda);
    k_main<<<GRID_MAIN, 256>>>(x, out);
}